// round 1
// baseline (speedup 1.0000x reference)
#include <cuda_runtime.h>

#define Bn 8
#define Sdim 1024
#define Ldim 1024
#define Hn 16
#define Dh 64
#define BHn 128
#define INV_TAU (1.0f/512.0f)

// Scratch (no cudaMalloc allowed)
__device__ float g_K[(size_t)Bn*Sdim*Ldim];
__device__ float g_Q[(size_t)Bn*Sdim*Ldim];
__device__ float g_O[(size_t)Bn*Sdim*Ldim];
__device__ float g_Z[(size_t)BHn*Ldim];

// ---------------------------------------------------------------------------
// proj: C[b] = W (SxS, row-major) @ X[b] (SxL) + bias    (batched over z)
// 128x128 block tile, K-step 16, 256 threads, 8x8 per thread (4+4 split).
// ---------------------------------------------------------------------------
__global__ __launch_bounds__(256) void proj_kernel(
    const float* __restrict__ W, const float* __restrict__ X,
    const float* __restrict__ bias, float* __restrict__ C) {
  __shared__ float As[16 * 132];   // A^T tile: As[k][row], stride 132
  __shared__ float Bs[16 * 128];   // Bs[k][col]
  const int b = blockIdx.z;
  const float* Xb = X + (size_t)b * Sdim * Ldim;
  float* Cb = C + (size_t)b * Sdim * Ldim;
  const int row0 = blockIdx.y * 128;
  const int col0 = blockIdx.x * 128;
  const int tid = threadIdx.x;
  const int tr = tid >> 4;
  const int tc = tid & 15;

  float acc[8][8];
#pragma unroll
  for (int i = 0; i < 8; i++)
#pragma unroll
    for (int j = 0; j < 8; j++) acc[i][j] = 0.0f;

  for (int k0 = 0; k0 < Sdim; k0 += 16) {
#pragma unroll
    for (int i = 0; i < 2; i++) {
      int idx = tid + i * 256;          // 0..511
      int ar = idx >> 2;                // 0..127 (row in tile)
      int ak = (idx & 3) * 4;           // 0,4,8,12 (k offset)
      float4 v = *(const float4*)&W[(size_t)(row0 + ar) * Sdim + k0 + ak];
      As[(ak + 0) * 132 + ar] = v.x;
      As[(ak + 1) * 132 + ar] = v.y;
      As[(ak + 2) * 132 + ar] = v.z;
      As[(ak + 3) * 132 + ar] = v.w;
      int br = idx >> 5;                // 0..15 (k row)
      int bc = (idx & 31) * 4;          // col offset
      *(float4*)&Bs[br * 128 + bc] =
          *(const float4*)&Xb[(size_t)(k0 + br) * Ldim + col0 + bc];
    }
    __syncthreads();
#pragma unroll
    for (int k = 0; k < 16; k++) {
      float4 a0 = *(float4*)&As[k * 132 + tr * 4];
      float4 a1 = *(float4*)&As[k * 132 + 64 + tr * 4];
      float4 b0 = *(float4*)&Bs[k * 128 + tc * 4];
      float4 b1 = *(float4*)&Bs[k * 128 + 64 + tc * 4];
      float a[8] = {a0.x, a0.y, a0.z, a0.w, a1.x, a1.y, a1.z, a1.w};
      float bb[8] = {b0.x, b0.y, b0.z, b0.w, b1.x, b1.y, b1.z, b1.w};
#pragma unroll
      for (int i = 0; i < 8; i++)
#pragma unroll
        for (int j = 0; j < 8; j++) acc[i][j] += a[i] * bb[j];
    }
    __syncthreads();
  }

#pragma unroll
  for (int i = 0; i < 8; i++) {
    int r = row0 + ((i < 4) ? (tr * 4 + i) : (64 + tr * 4 + i - 4));
    float bv = bias[r];
    float4 v0 = make_float4(acc[i][0] + bv, acc[i][1] + bv, acc[i][2] + bv, acc[i][3] + bv);
    float4 v1 = make_float4(acc[i][4] + bv, acc[i][5] + bv, acc[i][6] + bv, acc[i][7] + bv);
    *(float4*)&Cb[(size_t)r * Ldim + col0 + tc * 4] = v0;
    *(float4*)&Cb[(size_t)r * Ldim + col0 + 64 + tc * 4] = v1;
  }
}

// ---------------------------------------------------------------------------
// zpass: per (bh, 128-l-tile): Z[l] = sum_m exp( (sum_d K[d,l]*Q[d,m]) / tau )
// ---------------------------------------------------------------------------
__global__ __launch_bounds__(256) void zpass_kernel(
    const float* __restrict__ Kbuf, const float* __restrict__ Qbuf,
    float* __restrict__ Zbuf) {
  __shared__ float Ks[64 * 128];   // [d][l] full K tile for this l-block
  __shared__ float Qs[16 * 128];   // [d-chunk][m]
  const int bh = blockIdx.y;
  const int l0 = blockIdx.x * 128;
  const size_t base = ((size_t)(bh >> 4) * Sdim + (size_t)(bh & 15) * Dh) * Ldim;
  const float* Kh = Kbuf + base;
  const float* Qh = Qbuf + base;
  const int tid = threadIdx.x;
  const int tr = tid >> 4;
  const int tc = tid & 15;

#pragma unroll
  for (int i = 0; i < 8; i++) {
    int idx = tid + i * 256;            // 0..2047
    int r = idx >> 5;                   // d: 0..63
    int c = (idx & 31) * 4;             // l offset
    *(float4*)&Ks[r * 128 + c] = *(const float4*)&Kh[(size_t)r * Ldim + l0 + c];
  }
  __syncthreads();

  float rs[8];
#pragma unroll
  for (int i = 0; i < 8; i++) rs[i] = 0.0f;

  for (int m0 = 0; m0 < Ldim; m0 += 128) {
    float Sacc[8][8];
#pragma unroll
    for (int i = 0; i < 8; i++)
#pragma unroll
      for (int j = 0; j < 8; j++) Sacc[i][j] = 0.0f;

    for (int k0 = 0; k0 < 64; k0 += 16) {
#pragma unroll
      for (int i = 0; i < 2; i++) {
        int idx = tid + i * 256;
        int r = idx >> 5;
        int c = (idx & 31) * 4;
        *(float4*)&Qs[r * 128 + c] =
            *(const float4*)&Qh[(size_t)(k0 + r) * Ldim + m0 + c];
      }
      __syncthreads();
#pragma unroll
      for (int k = 0; k < 16; k++) {
        float4 a0 = *(float4*)&Ks[(k0 + k) * 128 + tr * 4];
        float4 a1 = *(float4*)&Ks[(k0 + k) * 128 + 64 + tr * 4];
        float4 b0 = *(float4*)&Qs[k * 128 + tc * 4];
        float4 b1 = *(float4*)&Qs[k * 128 + 64 + tc * 4];
        float a[8] = {a0.x, a0.y, a0.z, a0.w, a1.x, a1.y, a1.z, a1.w};
        float bb[8] = {b0.x, b0.y, b0.z, b0.w, b1.x, b1.y, b1.z, b1.w};
#pragma unroll
        for (int i = 0; i < 8; i++)
#pragma unroll
          for (int j = 0; j < 8; j++) Sacc[i][j] += a[i] * bb[j];
      }
      __syncthreads();
    }
#pragma unroll
    for (int i = 0; i < 8; i++)
#pragma unroll
      for (int j = 0; j < 8; j++) rs[i] += __expf(Sacc[i][j] * INV_TAU);
  }

  // reduce over the 16 threads (same tr) sharing each row group
#pragma unroll
  for (int i = 0; i < 8; i++) {
    float v = rs[i];
    v += __shfl_xor_sync(0xffffffffu, v, 1);
    v += __shfl_xor_sync(0xffffffffu, v, 2);
    v += __shfl_xor_sync(0xffffffffu, v, 4);
    v += __shfl_xor_sync(0xffffffffu, v, 8);
    rs[i] = v;
  }
  if (tc == 0) {
#pragma unroll
    for (int i = 0; i < 8; i++) {
      int lrow = (i < 4) ? (tr * 4 + i) : (64 + tr * 4 + i - 4);
      Zbuf[(size_t)bh * Ldim + l0 + lrow] = rs[i];
    }
  }
}

// ---------------------------------------------------------------------------
// opass: O[d,m] = sum_l (x[d,l]/Z[l]) * exp(S[l,m]/tau), recomputing S tiles.
// Block: one (bh, 128-m tile). Loops l in 64-chunks: phase A computes P tile
// into smem, phase B accumulates O (64 x 128) in registers.
// ---------------------------------------------------------------------------
__global__ __launch_bounds__(256) void opass_kernel(
    const float* __restrict__ x, const float* __restrict__ Kbuf,
    const float* __restrict__ Qbuf, const float* __restrict__ Zbuf,
    float* __restrict__ Obuf) {
  extern __shared__ float sm[];
  float* Qs = sm;             // 64*128 = 8192  [d][m] (whole block's Q tile)
  float* Zs = sm + 8192;      // 1024           Z row for this bh
  float* Ks = sm + 9216;      // 64*68 = 4352   [d][l-chunk], stride 68
  float* Xs = sm + 13568;     // 64*68 = 4352   [d][l-chunk] pre-divided by Z
  float* Ps = sm + 17920;     // 64*132 = 8448  [l][m], stride 132

  const int bh = blockIdx.y;
  const int m0 = blockIdx.x * 128;
  const size_t base = ((size_t)(bh >> 4) * Sdim + (size_t)(bh & 15) * Dh) * Ldim;
  const float* Kh = Kbuf + base;
  const float* Qh = Qbuf + base;
  const float* Xh = x + base;
  const int tid = threadIdx.x;
  const int tr = tid >> 4;
  const int tc = tid & 15;

#pragma unroll
  for (int i = 0; i < 8; i++) {
    int idx = tid + i * 256;
    int r = idx >> 5;
    int c = (idx & 31) * 4;
    *(float4*)&Qs[r * 128 + c] = *(const float4*)&Qh[(size_t)r * Ldim + m0 + c];
  }
  *(float4*)&Zs[tid * 4] = *(const float4*)&Zbuf[(size_t)bh * Ldim + tid * 4];
  __syncthreads();

  float Oacc[4][8];
#pragma unroll
  for (int i = 0; i < 4; i++)
#pragma unroll
    for (int j = 0; j < 8; j++) Oacc[i][j] = 0.0f;

  for (int l0 = 0; l0 < Ldim; l0 += 64) {
    // load K tile and scaled X tile for this l-chunk
#pragma unroll
    for (int i = 0; i < 4; i++) {
      int idx = tid + i * 256;          // 0..1023
      int r = idx >> 4;                 // d: 0..63
      int c = (idx & 15) * 4;           // l offset 0..60
      float4 kv = *(const float4*)&Kh[(size_t)r * Ldim + l0 + c];
      *(float4*)&Ks[r * 68 + c] = kv;
      float4 xv = *(const float4*)&Xh[(size_t)r * Ldim + l0 + c];
      xv.x /= Zs[l0 + c + 0];
      xv.y /= Zs[l0 + c + 1];
      xv.z /= Zs[l0 + c + 2];
      xv.w /= Zs[l0 + c + 3];
      *(float4*)&Xs[r * 68 + c] = xv;
    }
    __syncthreads();

    // Phase A: S tile (64 l x 128 m), rows l = tr*4+i
    float Sacc[4][8];
#pragma unroll
    for (int i = 0; i < 4; i++)
#pragma unroll
      for (int j = 0; j < 8; j++) Sacc[i][j] = 0.0f;
#pragma unroll 4
    for (int k = 0; k < 64; k++) {
      float4 a0 = *(float4*)&Ks[k * 68 + tr * 4];
      float4 b0 = *(float4*)&Qs[k * 128 + tc * 4];
      float4 b1 = *(float4*)&Qs[k * 128 + 64 + tc * 4];
      float a[4] = {a0.x, a0.y, a0.z, a0.w};
      float bb[8] = {b0.x, b0.y, b0.z, b0.w, b1.x, b1.y, b1.z, b1.w};
#pragma unroll
      for (int i = 0; i < 4; i++)
#pragma unroll
        for (int j = 0; j < 8; j++) Sacc[i][j] += a[i] * bb[j];
    }
#pragma unroll
    for (int i = 0; i < 4; i++) {
      int l = tr * 4 + i;
#pragma unroll
      for (int j = 0; j < 8; j++) {
        int m = (j < 4) ? (tc * 4 + j) : (64 + tc * 4 + j - 4);
        Ps[l * 132 + m] = __expf(Sacc[i][j] * INV_TAU);
      }
    }
    __syncthreads();

    // Phase B: O += X' (64d x 64l) @ P (64l x 128m)
#pragma unroll 4
    for (int l = 0; l < 64; l++) {
      float a[4];
#pragma unroll
      for (int i = 0; i < 4; i++) a[i] = Xs[(tr * 4 + i) * 68 + l];
      float4 b0 = *(float4*)&Ps[l * 132 + tc * 4];
      float4 b1 = *(float4*)&Ps[l * 132 + 64 + tc * 4];
      float bb[8] = {b0.x, b0.y, b0.z, b0.w, b1.x, b1.y, b1.z, b1.w};
#pragma unroll
      for (int i = 0; i < 4; i++)
#pragma unroll
        for (int j = 0; j < 8; j++) Oacc[i][j] += a[i] * bb[j];
    }
    __syncthreads();
  }

#pragma unroll
  for (int i = 0; i < 4; i++) {
    int d = tr * 4 + i;
    float* dst = Obuf + base + (size_t)d * Ldim + m0;
    *(float4*)&dst[tc * 4] = make_float4(Oacc[i][0], Oacc[i][1], Oacc[i][2], Oacc[i][3]);
    *(float4*)&dst[64 + tc * 4] = make_float4(Oacc[i][4], Oacc[i][5], Oacc[i][6], Oacc[i][7]);
  }
}

// ---------------------------------------------------------------------------
extern "C" void kernel_launch(void* const* d_in, const int* in_sizes, int n_in,
                              void* d_out, int out_size) {
  (void)in_sizes; (void)n_in; (void)out_size;
  const float* x  = (const float*)d_in[0];
  const float* y  = (const float*)d_in[1];
  const float* Wk = (const float*)d_in[2];
  const float* bk = (const float*)d_in[3];
  const float* Wq = (const float*)d_in[4];
  const float* bq = (const float*)d_in[5];
  const float* Wp = (const float*)d_in[6];
  const float* bp = (const float*)d_in[7];
  float* out = (float*)d_out;

  float *Kp, *Qp, *Op, *Zp;
  cudaGetSymbolAddress((void**)&Kp, g_K);
  cudaGetSymbolAddress((void**)&Qp, g_Q);
  cudaGetSymbolAddress((void**)&Op, g_O);
  cudaGetSymbolAddress((void**)&Zp, g_Z);

  const int opass_smem = 26368 * 4;  // 105,472 B
  cudaFuncSetAttribute(opass_kernel, cudaFuncAttributeMaxDynamicSharedMemorySize,
                       opass_smem);

  dim3 pg(8, 8, 8);
  proj_kernel<<<pg, 256>>>(Wk, x, bk, Kp);
  proj_kernel<<<pg, 256>>>(Wq, y, bq, Qp);
  zpass_kernel<<<dim3(8, 128), 256>>>(Kp, Qp, Zp);
  opass_kernel<<<dim3(8, 128), 256, opass_smem>>>(x, Kp, Qp, Zp, Op);
  proj_kernel<<<pg, 256>>>(Wp, Op, bp, out);
}

// round 2
// speedup vs baseline: 2.9907x; 2.9907x over previous
#include <cuda_runtime.h>

#define INV_TAU (1.0f/512.0f)

// Scratch (no cudaMalloc allowed)
__device__ float g_K[8ul*1024*1024];
__device__ float g_Q[8ul*1024*1024];
__device__ float g_O[8ul*1024*1024];
__device__ float g_Z[128ul*1024];

__device__ __forceinline__ unsigned f2t(float f) {
  unsigned u; asm("cvt.rna.tf32.f32 %0, %1;" : "=r"(u) : "f"(f)); return u;
}

__device__ __forceinline__ void mma8(float* c, unsigned a0, unsigned a1,
                                     unsigned a2, unsigned a3,
                                     unsigned b0, unsigned b1) {
  asm("mma.sync.aligned.m16n8k8.row.col.f32.tf32.tf32.f32 "
      "{%0,%1,%2,%3}, {%4,%5,%6,%7}, {%8,%9}, {%0,%1,%2,%3};"
      : "+f"(c[0]), "+f"(c[1]), "+f"(c[2]), "+f"(c[3])
      : "r"(a0), "r"(a1), "r"(a2), "r"(a3), "r"(b0), "r"(b1));
}

// ---------------------------------------------------------------------------
// proj: C[b] = W (1024x1024 row-major) @ X[b] (1024x1024) + bias
// Block tile 128x128, k-step 32. 8 warps in 2x4 grid; warp tile 64x32.
// As: [m][k] stride 36 (reads bank-free: 36%32=4). Bs: [k][n] stride 136 (%32=8).
// ---------------------------------------------------------------------------
__global__ __launch_bounds__(256) void proj_mma(
    const float* __restrict__ W, const float* __restrict__ X,
    const float* __restrict__ bias, float* __restrict__ C) {
  __shared__ unsigned As[128*36];
  __shared__ unsigned Bs[32*136];
  const int b = blockIdx.z;
  const float* Xb = X + (size_t)b*1024*1024;
  float* Cb = C + (size_t)b*1024*1024;
  const int row0 = blockIdx.y*128, col0 = blockIdx.x*128;
  const int tid = threadIdx.x, wid = tid>>5, lane = tid&31;
  const int gi = lane>>2, tj = lane&3;
  const int wm = (wid>>2)*64, wn = (wid&3)*32;

  float acc[4][4][4] = {};

  for (int k0 = 0; k0 < 1024; k0 += 32) {
#pragma unroll
    for (int i = 0; i < 4; i++) {
      int idx = tid + i*256;
      int r = idx>>3, k4 = (idx&7)*4;
      float4 v = *(const float4*)&W[(size_t)(row0+r)*1024 + k0 + k4];
      unsigned* p = &As[r*36 + k4];
      p[0]=f2t(v.x); p[1]=f2t(v.y); p[2]=f2t(v.z); p[3]=f2t(v.w);
    }
#pragma unroll
    for (int i = 0; i < 4; i++) {
      int idx = tid + i*256;
      int kk = idx>>5, n4 = (idx&31)*4;
      float4 v = *(const float4*)&Xb[(size_t)(k0+kk)*1024 + col0 + n4];
      unsigned* p = &Bs[kk*136 + n4];
      p[0]=f2t(v.x); p[1]=f2t(v.y); p[2]=f2t(v.z); p[3]=f2t(v.w);
    }
    __syncthreads();
#pragma unroll
    for (int c = 0; c < 4; c++) {
      const int kb = c*8;
      unsigned a[4][4], bb[4][2];
#pragma unroll
      for (int mt = 0; mt < 4; mt++) {
        int m = wm + mt*16;
        a[mt][0] = As[(m+gi)*36 + kb + tj];
        a[mt][1] = As[(m+8+gi)*36 + kb + tj];
        a[mt][2] = As[(m+gi)*36 + kb+4 + tj];
        a[mt][3] = As[(m+8+gi)*36 + kb+4 + tj];
      }
#pragma unroll
      for (int nt = 0; nt < 4; nt++) {
        int n = wn + nt*8 + gi;
        bb[nt][0] = Bs[(kb+tj)*136 + n];
        bb[nt][1] = Bs[(kb+4+tj)*136 + n];
      }
#pragma unroll
      for (int mt = 0; mt < 4; mt++)
#pragma unroll
        for (int nt = 0; nt < 4; nt++)
          mma8(acc[mt][nt], a[mt][0],a[mt][1],a[mt][2],a[mt][3],
               bb[nt][0], bb[nt][1]);
    }
    __syncthreads();
  }
#pragma unroll
  for (int mt = 0; mt < 4; mt++) {
    int r0 = row0 + wm + mt*16 + gi;
    float bv0 = bias[r0], bv1 = bias[r0+8];
#pragma unroll
    for (int nt = 0; nt < 4; nt++) {
      int cc = col0 + wn + nt*8 + 2*tj;
      *(float2*)&Cb[(size_t)r0*1024 + cc] =
          make_float2(acc[mt][nt][0]+bv0, acc[mt][nt][1]+bv0);
      *(float2*)&Cb[(size_t)(r0+8)*1024 + cc] =
          make_float2(acc[mt][nt][2]+bv1, acc[mt][nt][3]+bv1);
    }
  }
}

// ---------------------------------------------------------------------------
// zpass: Z[l] = sum_m exp(S[l,m]/tau), S = K^T Q (contraction over d=64).
// K,Q both [d][l] in gmem -> NO transpose: A-frags of K^T read natural layout.
// Block: one (bh, 128-l tile); loops m in 128 chunks. Warps 2(l) x 4(m).
// ---------------------------------------------------------------------------
__global__ __launch_bounds__(256) void zpass_mma(
    const float* __restrict__ Kbuf, const float* __restrict__ Qbuf,
    float* __restrict__ Zbuf) {
  extern __shared__ unsigned zsm[];
  unsigned* Ks = zsm;                       // 64*136
  unsigned* Qs = zsm + 64*136;              // 64*136
  float* Zpart = (float*)(zsm + 2*64*136);  // 4*128
  const int bh = blockIdx.y, l0 = blockIdx.x*128;
  const size_t base = ((size_t)(bh>>4)*1024 + (size_t)(bh&15)*64)*1024;
  const float* Kh = Kbuf + base;
  const float* Qh = Qbuf + base;
  const int tid = threadIdx.x, wid = tid>>5, lane = tid&31;
  const int gi = lane>>2, tj = lane&3;
  const int wl = (wid>>2)*64, wnn = (wid&3)*32;

#pragma unroll
  for (int i = 0; i < 8; i++) {
    int idx = tid + i*256;
    int r = idx>>5, c4 = (idx&31)*4;
    float4 v = *(const float4*)&Kh[(size_t)r*1024 + l0 + c4];
    unsigned* p = &Ks[r*136 + c4];
    p[0]=f2t(v.x); p[1]=f2t(v.y); p[2]=f2t(v.z); p[3]=f2t(v.w);
  }
  float rs[8] = {};

  for (int m0 = 0; m0 < 1024; m0 += 128) {
    __syncthreads();
#pragma unroll
    for (int i = 0; i < 8; i++) {
      int idx = tid + i*256;
      int r = idx>>5, c4 = (idx&31)*4;
      float4 v = *(const float4*)&Qh[(size_t)r*1024 + m0 + c4];
      unsigned* p = &Qs[r*136 + c4];
      p[0]=f2t(v.x); p[1]=f2t(v.y); p[2]=f2t(v.z); p[3]=f2t(v.w);
    }
    __syncthreads();
    float S[4][4][4] = {};
#pragma unroll
    for (int db = 0; db < 64; db += 8) {
      unsigned a[4][4], bb[4][2];
#pragma unroll
      for (int mt = 0; mt < 4; mt++) {
        int l = wl + mt*16;
        a[mt][0] = Ks[(db+tj)*136 + l + gi];
        a[mt][1] = Ks[(db+tj)*136 + l + 8 + gi];
        a[mt][2] = Ks[(db+4+tj)*136 + l + gi];
        a[mt][3] = Ks[(db+4+tj)*136 + l + 8 + gi];
      }
#pragma unroll
      for (int nt = 0; nt < 4; nt++) {
        int n = wnn + nt*8 + gi;
        bb[nt][0] = Qs[(db+tj)*136 + n];
        bb[nt][1] = Qs[(db+4+tj)*136 + n];
      }
#pragma unroll
      for (int mt = 0; mt < 4; mt++)
#pragma unroll
        for (int nt = 0; nt < 4; nt++)
          mma8(S[mt][nt], a[mt][0],a[mt][1],a[mt][2],a[mt][3],
               bb[nt][0], bb[nt][1]);
    }
#pragma unroll
    for (int mt = 0; mt < 4; mt++)
#pragma unroll
      for (int nt = 0; nt < 4; nt++) {
        rs[2*mt]   += __expf(S[mt][nt][0]*INV_TAU) + __expf(S[mt][nt][1]*INV_TAU);
        rs[2*mt+1] += __expf(S[mt][nt][2]*INV_TAU) + __expf(S[mt][nt][3]*INV_TAU);
      }
  }
#pragma unroll
  for (int i = 0; i < 8; i++) {
    rs[i] += __shfl_xor_sync(0xffffffffu, rs[i], 1);
    rs[i] += __shfl_xor_sync(0xffffffffu, rs[i], 2);
  }
  if (tj == 0) {
#pragma unroll
    for (int mt = 0; mt < 4; mt++) {
      Zpart[(wid&3)*128 + wl + mt*16 + gi]     = rs[2*mt];
      Zpart[(wid&3)*128 + wl + mt*16 + 8 + gi] = rs[2*mt+1];
    }
  }
  __syncthreads();
  if (tid < 128) {
    float z = Zpart[tid] + Zpart[128+tid] + Zpart[256+tid] + Zpart[384+tid];
    Zbuf[(size_t)bh*1024 + l0 + tid] = z;
  }
}

// ---------------------------------------------------------------------------
// opass: O[d,m] = sum_l (x[d,l]/Z[l]) * exp(S[l,m]/tau), flash-style.
// Block: one (bh, 128-m tile); l in 64 chunks. GEMM1 (S) then GEMM2 (O).
// Warps: 2(rows) x 4(m). Oacc persistent in C-fragments.
// ---------------------------------------------------------------------------
__global__ __launch_bounds__(256) void opass_mma(
    const float* __restrict__ x, const float* __restrict__ Kbuf,
    const float* __restrict__ Qbuf, const float* __restrict__ Zbuf,
    float* __restrict__ Obuf) {
  extern __shared__ unsigned osm[];
  unsigned* Qs  = osm;                         // 64*136 = 8704
  unsigned* Ksc = osm + 8704;                  // 64*72  = 4608
  unsigned* Xs  = osm + 8704 + 4608;           // 64*68  = 4352
  unsigned* Ps  = osm + 8704 + 4608 + 4352;    // 64*136 = 8704
  float* Zr = (float*)(osm + 8704 + 4608 + 4352 + 8704);  // 1024
  const int bh = blockIdx.y, m0 = blockIdx.x*128;
  const size_t base = ((size_t)(bh>>4)*1024 + (size_t)(bh&15)*64)*1024;
  const float* Kh = Kbuf + base;
  const float* Qh = Qbuf + base;
  const float* Xh = x + base;
  const int tid = threadIdx.x, wid = tid>>5, lane = tid&31;
  const int gi = lane>>2, tj = lane&3;
  const int wr = (wid>>2)*32;   // l-rows (GEMM1) / d-rows (GEMM2)
  const int wn = (wid&3)*32;    // m-cols

#pragma unroll
  for (int i = 0; i < 8; i++) {
    int idx = tid + i*256;
    int r = idx>>5, c4 = (idx&31)*4;
    float4 v = *(const float4*)&Qh[(size_t)r*1024 + m0 + c4];
    unsigned* p = &Qs[r*136 + c4];
    p[0]=f2t(v.x); p[1]=f2t(v.y); p[2]=f2t(v.z); p[3]=f2t(v.w);
  }
  {
    float4 z = *(const float4*)&Zbuf[(size_t)bh*1024 + tid*4];
    Zr[tid*4+0] = __frcp_rn(z.x);
    Zr[tid*4+1] = __frcp_rn(z.y);
    Zr[tid*4+2] = __frcp_rn(z.z);
    Zr[tid*4+3] = __frcp_rn(z.w);
  }

  float O[2][4][4] = {};

  for (int l0 = 0; l0 < 1024; l0 += 64) {
    __syncthreads();
#pragma unroll
    for (int i = 0; i < 4; i++) {
      int idx = tid + i*256;
      int r = idx>>4, c4 = (idx&15)*4;
      float4 kv = *(const float4*)&Kh[(size_t)r*1024 + l0 + c4];
      unsigned* p = &Ksc[r*72 + c4];
      p[0]=f2t(kv.x); p[1]=f2t(kv.y); p[2]=f2t(kv.z); p[3]=f2t(kv.w);
      float4 xv = *(const float4*)&Xh[(size_t)r*1024 + l0 + c4];
      xv.x *= Zr[l0+c4+0]; xv.y *= Zr[l0+c4+1];
      xv.z *= Zr[l0+c4+2]; xv.w *= Zr[l0+c4+3];
      unsigned* q = &Xs[r*68 + c4];
      q[0]=f2t(xv.x); q[1]=f2t(xv.y); q[2]=f2t(xv.z); q[3]=f2t(xv.w);
    }
    __syncthreads();
    // GEMM1: S chunk = K^T(64l x 64d) @ Q(64d x 128m)
    float S[2][4][4] = {};
#pragma unroll
    for (int db = 0; db < 64; db += 8) {
      unsigned a[2][4], bb[4][2];
#pragma unroll
      for (int mt = 0; mt < 2; mt++) {
        int l = wr + mt*16;
        a[mt][0] = Ksc[(db+tj)*72 + l + gi];
        a[mt][1] = Ksc[(db+tj)*72 + l + 8 + gi];
        a[mt][2] = Ksc[(db+4+tj)*72 + l + gi];
        a[mt][3] = Ksc[(db+4+tj)*72 + l + 8 + gi];
      }
#pragma unroll
      for (int nt = 0; nt < 4; nt++) {
        int n = wn + nt*8 + gi;
        bb[nt][0] = Qs[(db+tj)*136 + n];
        bb[nt][1] = Qs[(db+4+tj)*136 + n];
      }
#pragma unroll
      for (int mt = 0; mt < 2; mt++)
#pragma unroll
        for (int nt = 0; nt < 4; nt++)
          mma8(S[mt][nt], a[mt][0],a[mt][1],a[mt][2],a[mt][3],
               bb[nt][0], bb[nt][1]);
    }
    // exp -> Ps (tf32)
#pragma unroll
    for (int mt = 0; mt < 2; mt++) {
      int l = wr + mt*16 + gi;
#pragma unroll
      for (int nt = 0; nt < 4; nt++) {
        int m = wn + nt*8 + 2*tj;
        Ps[l*136 + m]       = f2t(__expf(S[mt][nt][0]*INV_TAU));
        Ps[l*136 + m + 1]   = f2t(__expf(S[mt][nt][1]*INV_TAU));
        Ps[(l+8)*136 + m]     = f2t(__expf(S[mt][nt][2]*INV_TAU));
        Ps[(l+8)*136 + m + 1] = f2t(__expf(S[mt][nt][3]*INV_TAU));
      }
    }
    __syncthreads();
    // GEMM2: O += X'(64d x 64l) @ P(64l x 128m)
#pragma unroll
    for (int lb = 0; lb < 64; lb += 8) {
      unsigned a[2][4], bb[4][2];
#pragma unroll
      for (int mt = 0; mt < 2; mt++) {
        int d = wr + mt*16;
        a[mt][0] = Xs[(d+gi)*68 + lb + tj];
        a[mt][1] = Xs[(d+8+gi)*68 + lb + tj];
        a[mt][2] = Xs[(d+gi)*68 + lb + 4 + tj];
        a[mt][3] = Xs[(d+8+gi)*68 + lb + 4 + tj];
      }
#pragma unroll
      for (int nt = 0; nt < 4; nt++) {
        int n = wn + nt*8 + gi;
        bb[nt][0] = Ps[(lb+tj)*136 + n];
        bb[nt][1] = Ps[(lb+4+tj)*136 + n];
      }
#pragma unroll
      for (int mt = 0; mt < 2; mt++)
#pragma unroll
        for (int nt = 0; nt < 4; nt++)
          mma8(O[mt][nt], a[mt][0],a[mt][1],a[mt][2],a[mt][3],
               bb[nt][0], bb[nt][1]);
    }
  }
#pragma unroll
  for (int mt = 0; mt < 2; mt++) {
    int d = wr + mt*16 + gi;
#pragma unroll
    for (int nt = 0; nt < 4; nt++) {
      int c = m0 + wn + nt*8 + 2*tj;
      *(float2*)&Obuf[base + (size_t)d*1024 + c] =
          make_float2(O[mt][nt][0], O[mt][nt][1]);
      *(float2*)&Obuf[base + (size_t)(d+8)*1024 + c] =
          make_float2(O[mt][nt][2], O[mt][nt][3]);
    }
  }
}

// ---------------------------------------------------------------------------
extern "C" void kernel_launch(void* const* d_in, const int* in_sizes, int n_in,
                              void* d_out, int out_size) {
  (void)in_sizes; (void)n_in; (void)out_size;
  const float* x  = (const float*)d_in[0];
  const float* y  = (const float*)d_in[1];
  const float* Wk = (const float*)d_in[2];
  const float* bk = (const float*)d_in[3];
  const float* Wq = (const float*)d_in[4];
  const float* bq = (const float*)d_in[5];
  const float* Wp = (const float*)d_in[6];
  const float* bp = (const float*)d_in[7];
  float* out = (float*)d_out;

  float *Kp, *Qp, *Op, *Zp;
  cudaGetSymbolAddress((void**)&Kp, g_K);
  cudaGetSymbolAddress((void**)&Qp, g_Q);
  cudaGetSymbolAddress((void**)&Op, g_O);
  cudaGetSymbolAddress((void**)&Zp, g_Z);

  const int zsmem = (2*64*136 + 4*128) * 4;                    // 71,680 B
  const int osmem = (8704 + 4608 + 4352 + 8704 + 1024) * 4;    // 109,568 B
  cudaFuncSetAttribute(zpass_mma, cudaFuncAttributeMaxDynamicSharedMemorySize, zsmem);
  cudaFuncSetAttribute(opass_mma, cudaFuncAttributeMaxDynamicSharedMemorySize, osmem);

  dim3 pg(8, 8, 8);
  proj_mma<<<pg, 256>>>(Wk, x, bk, Kp);
  proj_mma<<<pg, 256>>>(Wq, y, bq, Qp);
  zpass_mma<<<dim3(8, 128), 256, zsmem>>>(Kp, Qp, Zp);
  opass_mma<<<dim3(8, 128), 256, osmem>>>(x, Kp, Qp, Zp, Op);
  proj_mma<<<pg, 256>>>(Wp, Op, bp, out);
}